// round 11
// baseline (speedup 1.0000x reference)
#include <cuda_runtime.h>
#include <cstdint>

// AdditiveAttention: out[b,q,v] = softmax_k( sum_h w_v[h]*tanh(q~[b,q,h]+k~[b,k,h]) ) @ V
// B=4, Q=256, K=1024, IN=256, H=128, V=256.

typedef unsigned long long ull;

// Scratch (__device__ globals — no allocation allowed)
__device__ float g_wqt[256 * 128];            // W_q^T [in][h]
__device__ float g_wkt[256 * 128];            // W_k^T [in][h]
__device__ float g_qp[4 * 256 * 128];         // projected queries
__device__ float g_kp[4 * 1024 * 128];        // projected keys
__device__ float g_pacc[32 * 256 * 256];      // partial acc [b*8+kq][q][v]
__device__ float g_psum[32 * 256];            // partial exp-sums [b*8+kq][q]
__device__ unsigned int g_flag_t;             // transpose-done counter (self-reset)
__device__ unsigned int g_done_p;             // prep completion counter (self-reset)
__device__ unsigned int g_cnt[128];           // per-(b,qt) partial counters (self-reset)

__device__ __forceinline__ float tanh_apx(float x) {
    float y;
    asm("tanh.approx.f32 %0, %1;" : "=f"(y) : "f"(x));
    return y;
}

__device__ __forceinline__ void fma2(ull& d, ull a, ull b) {
    asm("fma.rn.f32x2 %0, %1, %2, %0;" : "+l"(d) : "l"(a), "l"(b));
}

__device__ __forceinline__ ull pack2(float x) {
    ull r;
    asm("mov.b64 %0, {%1, %1};" : "=l"(r) : "f"(x));
    return r;
}

__device__ __forceinline__ void ldgsts16(uint32_t saddr, const void* g) {
    asm volatile("cp.async.cg.shared.global [%0], [%1], 16;"
                 :: "r"(saddr), "l"(g));
}
__device__ __forceinline__ void cp_commit() {
    asm volatile("cp.async.commit_group;" ::: "memory");
}
__device__ __forceinline__ void cp_wait0() {
    asm volatile("cp.async.wait_group 0;" ::: "memory");
}

// ---------------------------------------------------------------------------
// K_prep: fused weight transpose + projections (unchanged from R10).
// 160 blocks x 256 threads; blocks 0-63 transpose W then all project 32 rows.
// ---------------------------------------------------------------------------
#define SMEM_PREP (36864 + 32768)   // xs2 [256][18]f2 + wt [2][32*128]f

__global__ __launch_bounds__(256, 2) void k_prep(
    const float* __restrict__ queries, const float* __restrict__ keys,
    const float* __restrict__ Wq, const float* __restrict__ Wk) {
    extern __shared__ float psm[];
    float2* xs2 = (float2*)psm;          // [256][18] float2
    float*  wt  = psm + 9216;            // [2][4096] floats
    __shared__ float ttile[32][33];

    int bid = blockIdx.x;
    int t = threadIdx.x;

    // ---- Phase T: transpose (blocks 0-63) ----
    if (bid < 64) {
        int m = bid >> 5;
        int tb = bid & 31;
        int hb = tb >> 3, ib = tb & 7;
        const float* W = m ? Wk : Wq;
        float* Wt = m ? g_wkt : g_wqt;
        int c = t & 31, r0 = t >> 5;
        #pragma unroll
        for (int rr = 0; rr < 4; ++rr) {
            int r = r0 * 4 + rr;
            ttile[r][c] = W[(hb * 32 + r) * 256 + ib * 32 + c];
        }
        __syncthreads();
        #pragma unroll
        for (int rr = 0; rr < 4; ++rr) {
            int r = r0 * 4 + rr;
            Wt[(ib * 32 + r) * 128 + hb * 32 + c] = ttile[c][r];
        }
        __threadfence();
        __syncthreads();
        if (t == 0) atomicAdd(&g_flag_t, 1u);
    }

    // ---- spin until all 64 transpose blocks done ----
    if (t == 0) {
        while (atomicAdd(&g_flag_t, 0u) < 64u) {}
        __threadfence();
    }
    __syncthreads();

    // ---- Phase P: projection of 32 rows ----
    const float* src;
    const float* Wt;
    float* dst;
    int r0g;
    if (bid < 128) { src = keys;    Wt = g_wkt; dst = g_kp; r0g = bid * 32; }
    else           { src = queries; Wt = g_wqt; dst = g_qp; r0g = (bid - 128) * 32; }

    uint32_t wtaddr = (uint32_t)__cvta_generic_to_shared(wt);
    const float4* Wt4 = (const float4*)Wt;

    #pragma unroll
    for (int n = 0; n < 4; ++n) {
        int idx = t + n * 256;
        ldgsts16(wtaddr + (uint32_t)(idx * 16), Wt4 + idx);
    }
    cp_commit();

    const float4* s4 = (const float4*)(src + r0g * 256);
    float* xsf = (float*)xs2;
    #pragma unroll 4
    for (int n = 0; n < 8; ++n) {
        int idx4 = t + n * 256;
        int r = idx4 >> 6, i4 = idx4 & 63;
        float4 v = s4[idx4];
        xsf[(i4 * 4 + 0) * 36 + r] = v.x;
        xsf[(i4 * 4 + 1) * 36 + r] = v.y;
        xsf[(i4 * 4 + 2) * 36 + r] = v.z;
        xsf[(i4 * 4 + 3) * 36 + r] = v.w;
    }
    cp_wait0();

    int h2 = (t & 63) * 2;
    int rh = t >> 6;
    const float2* xp = xs2 + rh * 4;
    ull acc[4][2] = {{0ull,0ull},{0ull,0ull},{0ull,0ull},{0ull,0ull}};

    for (int tau = 0; tau < 8; ++tau) {
        __syncthreads();
        if (tau + 1 < 8) {
            int buf = (tau + 1) & 1;
            const float4* srcw = Wt4 + (tau + 1) * 1024;
            #pragma unroll
            for (int n = 0; n < 4; ++n) {
                int idx = t + n * 256;
                ldgsts16(wtaddr + (uint32_t)(buf * 16384 + idx * 16), srcw + idx);
            }
            cp_commit();
        }
        const float* wb = wt + (tau & 1) * 4096;
        #pragma unroll 8
        for (int ii = 0; ii < 32; ++ii) {
            float2 w2 = *(const float2*)&wb[ii * 128 + h2];
            ull wa = pack2(w2.x);
            ull wbp = pack2(w2.y);
            const float2* xi = xp + (tau * 32 + ii) * 18;
            ull x0 = *(const ull*)&xi[0];
            ull x1 = *(const ull*)&xi[1];
            ull x2 = *(const ull*)&xi[2];
            ull x3 = *(const ull*)&xi[3];
            fma2(acc[0][0], x0, wa); fma2(acc[0][1], x0, wbp);
            fma2(acc[1][0], x1, wa); fma2(acc[1][1], x1, wbp);
            fma2(acc[2][0], x2, wa); fma2(acc[2][1], x2, wbp);
            fma2(acc[3][0], x3, wa); fma2(acc[3][1], x3, wbp);
        }
        cp_wait0();
    }

    #pragma unroll
    for (int p = 0; p < 4; ++p) {
        float2 A = *(float2*)&acc[p][0];
        float2 Bv = *(float2*)&acc[p][1];
        int r = r0g + rh * 8 + p * 2;
        float2 o0 = make_float2(A.x, Bv.x);
        float2 o1 = make_float2(A.y, Bv.y);
        *(float2*)&dst[r * 128 + h2] = o0;
        *(float2*)&dst[(r + 1) * 128 + h2] = o1;
    }

    __syncthreads();
    if (t == 0) {
        if (atomicAdd(&g_done_p, 1u) == 159u) {
            atomicExch(&g_flag_t, 0u);
            atomicExch(&g_done_p, 0u);
        }
    }
}

// ---------------------------------------------------------------------------
// K_attn6: split-K attn, high-occupancy rework.
// 1024 blocks: b = bid&3, kq = (bid>>2)&7, qt = bid>>5.
// Block covers 8 queries x 128 keys as <=4 chunks of 32 k. ks double-buffered
// cp.async with rotation swizzle; SMEM 41.5 KB, regs capped 64 -> 4 blocks/SM.
// Phase A: thread (qa = t>>5 [warp-uniform], ka = t&31), 4 independent score
//   accumulators (breaks the fmaf chain). e = expf(s) (bounded), no max pass.
// Phase C (fused with next A): thread (qc = t>>5, 8 v-cols), 4 f32x2 accs.
// Combine-on-last-arrival per (b,qt) over np = ceil(vlen/128) partials.
// ---------------------------------------------------------------------------
#define SMEM_ATTN ((8192 + 1024 + 128 + 2048 + 8) * 4)   // 41.5 KB

__global__ __launch_bounds__(256, 4) void k_attn6(
    const float* __restrict__ values, const int* __restrict__ valid_lens,
    const float* __restrict__ w_v, float* __restrict__ out) {
    extern __shared__ float sm[];
    float4* ks4  = (float4*)sm;                      // [2][32*32] float4
    float*  qs   = sm + 8192;                        // [8][128]
    float*  wvs  = qs + 1024;                        // [128]
    float2* eb2  = (float2*)(wvs + 128);             // [2][8*32] = {e,e}
    float*  wsum = (float*)(eb2 + 512);              // [8]
    __shared__ unsigned int s_old;

    int bid = blockIdx.x;
    int b = bid & 3;
    int kq = (bid >> 2) & 7;
    int qt = bid >> 5;                // 0..31
    int vlen = valid_lens[b];
    int k0 = kq * 128;
    if (k0 >= vlen) return;
    int nch = min(4, (vlen - k0 + 31) >> 5);

    int t = threadIdx.x;
    int q0 = qt * 8;
    int qa = t >> 5;                  // warp-uniform q (0..7)
    int ka = t & 31;                  // A: key index within chunk
    int vp = (t & 31) * 8;            // C: 8 v-cols

    const float4* kp4 = (const float4*)(g_kp + (b * 1024 + k0) * 128);
    const float* Vb = values + (b * 1024 + k0) * 256;
    uint32_t ksaddr = (uint32_t)__cvta_generic_to_shared(ks4);

    // ---- issue chunk 0 copy (32 k x 32 float4) ----
    #pragma unroll
    for (int n = 0; n < 4; ++n) {
        int idx = t + n * 256;                // 0..1023
        int kk = idx >> 5, h4 = idx & 31;
        uint32_t d = ksaddr + (uint32_t)((kk * 32 + ((h4 + kk) & 31)) * 16);
        ldgsts16(d, kp4 + kk * 32 + h4);
    }
    cp_commit();

    // ---- load qs (8 rows), wvs while copy flies ----
    for (int i = t; i < 1024; i += 256)
        qs[i] = g_qp[(b * 256 + q0) * 128 + i];
    if (t < 128) wvs[t] = w_v[t];
    cp_wait0();

    ull acc0 = 0ull, acc1 = 0ull, acc2 = 0ull, acc3 = 0ull;
    float lsum = 0.f;
    const float* qrow = qs + qa * 128;

    for (int c = 0; c < nch; ++c) {
        __syncthreads();   // chunk c copies + ebuf(c-1) visible

        if (c + 1 < nch) {
            int buf = (c + 1) & 1;
            const float4* srcc = kp4 + (c + 1) * 1024;
            #pragma unroll
            for (int n = 0; n < 4; ++n) {
                int idx = t + n * 256;
                int kk = idx >> 5, h4 = idx & 31;
                uint32_t d = ksaddr +
                    (uint32_t)((buf * 1024 + kk * 32 + ((h4 + kk) & 31)) * 16);
                ldgsts16(d, srcc + kk * 32 + h4);
            }
            cp_commit();
        }

        const float4* ksb = ks4 + (c & 1) * 1024 + ka * 32;
        float s0 = 0.f, s1 = 0.f, s2 = 0.f, s3 = 0.f;  // 4 indep chains

        if (c == 0) {
            #pragma unroll 8
            for (int j = 0; j < 32; ++j) {
                float4 kv = ksb[(j + ka) & 31];
                float4 q4 = *(const float4*)&qrow[j * 4];
                float4 w4 = *(const float4*)&wvs[j * 4];
                s0 = fmaf(w4.x, tanh_apx(q4.x + kv.x), s0);
                s1 = fmaf(w4.y, tanh_apx(q4.y + kv.y), s1);
                s2 = fmaf(w4.z, tanh_apx(q4.z + kv.z), s2);
                s3 = fmaf(w4.w, tanh_apx(q4.w + kv.w), s3);
            }
        } else {
            const float2* eb = eb2 + ((c & 1) ^ 1) * 256 + qa * 32;
            const float* Vp = Vb + (c - 1) * 32 * 256 + vp;
            #pragma unroll 4
            for (int j = 0; j < 32; ++j) {
                float4 kv = ksb[(j + ka) & 31];
                float4 q4 = *(const float4*)&qrow[j * 4];
                float4 w4 = *(const float4*)&wvs[j * 4];
                s0 = fmaf(w4.x, tanh_apx(q4.x + kv.x), s0);
                s1 = fmaf(w4.y, tanh_apx(q4.y + kv.y), s1);
                s2 = fmaf(w4.z, tanh_apx(q4.z + kv.z), s2);
                s3 = fmaf(w4.w, tanh_apx(q4.w + kv.w), s3);
                float2 e0 = eb[j];
                float4 v0 = *(const float4*)&Vp[j * 256];
                float4 v1 = *(const float4*)&Vp[j * 256 + 4];
                fma2(acc0, *(ull*)&e0, *(ull*)&v0.x);
                fma2(acc1, *(ull*)&e0, *(ull*)&v0.z);
                fma2(acc2, *(ull*)&e0, *(ull*)&v1.x);
                fma2(acc3, *(ull*)&e0, *(ull*)&v1.z);
            }
        }

        int kg = k0 + c * 32 + ka;
        float s = (s0 + s1) + (s2 + s3);
        float e = (kg < vlen) ? __expf(s) : 0.f;
        eb2[(c & 1) * 256 + qa * 32 + ka] = make_float2(e, e);
        lsum += e;
        if (c + 1 < nch) cp_wait0();
    }

    // ---- epilogue: C(nch-1) ----
    __syncthreads();
    {
        const float2* eb = eb2 + ((nch - 1) & 1) * 256 + qa * 32;
        const float* Vp = Vb + (nch - 1) * 32 * 256 + vp;
        #pragma unroll 4
        for (int kk = 0; kk < 32; ++kk) {
            float2 e0 = eb[kk];
            float4 v0 = *(const float4*)&Vp[kk * 256];
            float4 v1 = *(const float4*)&Vp[kk * 256 + 4];
            fma2(acc0, *(ull*)&e0, *(ull*)&v0.x);
            fma2(acc1, *(ull*)&e0, *(ull*)&v0.z);
            fma2(acc2, *(ull*)&e0, *(ull*)&v1.x);
            fma2(acc3, *(ull*)&e0, *(ull*)&v1.z);
        }
    }

    // per-q exp sums: warp w == q row (qa warp-uniform, lanes = ka)
    lsum += __shfl_xor_sync(0xffffffffu, lsum, 16);
    lsum += __shfl_xor_sync(0xffffffffu, lsum, 8);
    lsum += __shfl_xor_sync(0xffffffffu, lsum, 4);
    lsum += __shfl_xor_sync(0xffffffffu, lsum, 2);
    lsum += __shfl_xor_sync(0xffffffffu, lsum, 1);
    int lane = t & 31;
    if (lane == 0) wsum[qa] = lsum;
    __syncthreads();
    if (t < 8)
        g_psum[(b * 8 + kq) * 256 + q0 + t] = wsum[t];

    // partial acc write (unnormalized): 8 v per thread
    {
        float* pa = &g_pacc[(((b * 8 + kq) * 256) + q0 + qa) * 256 + vp];
        float4 o0, o1;
        o0.x = ((float2*)&acc0)->x; o0.y = ((float2*)&acc0)->y;
        o0.z = ((float2*)&acc1)->x; o0.w = ((float2*)&acc1)->y;
        o1.x = ((float2*)&acc2)->x; o1.y = ((float2*)&acc2)->y;
        o1.z = ((float2*)&acc3)->x; o1.w = ((float2*)&acc3)->y;
        *(float4*)pa = o0;
        *(float4*)(pa + 4) = o1;
    }

    // ---- combine-on-last-arrival ----
    __threadfence();
    __syncthreads();
    if (t == 0) s_old = atomicAdd(&g_cnt[b * 32 + qt], 1u);
    __syncthreads();

    int np = (vlen + 127) >> 7;           // participants for this (b, qt): 1..8
    if (s_old == (unsigned)(np - 1)) {
        __threadfence();                  // acquire: peers' partials visible
        #pragma unroll
        for (int qi = 0; qi < 8; ++qi) {
            int qq = q0 + qi;
            float a = 0.f, s = 0.f;
            for (int p = 0; p < np; ++p) {
                a += g_pacc[((b * 8 + p) * 256 + qq) * 256 + t];
                s += g_psum[(b * 8 + p) * 256 + qq];
            }
            out[(b * 256 + qq) * 256 + t] = a / s;
        }
        if (t == 0) atomicExch(&g_cnt[b * 32 + qt], 0u);
    }
}

// ---------------------------------------------------------------------------
extern "C" void kernel_launch(void* const* d_in, const int* in_sizes, int n_in,
                              void* d_out, int out_size) {
    const float* queries    = (const float*)d_in[0];  // [4,256,256]
    const float* keys       = (const float*)d_in[1];  // [4,1024,256]
    const float* values     = (const float*)d_in[2];  // [4,1024,256]
    const int*   valid_lens = (const int*)d_in[3];    // [4]
    const float* W_q        = (const float*)d_in[4];  // [128,256]
    const float* W_k        = (const float*)d_in[5];  // [128,256]
    const float* w_v        = (const float*)d_in[6];  // [128]
    float* out = (float*)d_out;                       // [4,256,256]

    cudaFuncSetAttribute(k_prep, cudaFuncAttributeMaxDynamicSharedMemorySize,
                         SMEM_PREP);
    cudaFuncSetAttribute(k_attn6, cudaFuncAttributeMaxDynamicSharedMemorySize,
                         SMEM_ATTN);

    k_prep<<<160, 256, SMEM_PREP>>>(queries, keys, W_q, W_k);
    k_attn6<<<1024, 256, SMEM_ATTN>>>(values, valid_lens, w_v, out);
}

// round 12
// speedup vs baseline: 1.2205x; 1.2205x over previous
#include <cuda_runtime.h>
#include <cstdint>

// AdditiveAttention: out[b,q,v] = softmax_k( sum_h w_v[h]*tanh(q~[b,q,h]+k~[b,k,h]) ) @ V
// B=4, Q=256, K=1024, IN=256, H=128, V=256.

typedef unsigned long long ull;

// Scratch (__device__ globals — no allocation allowed)
__device__ float g_wqt[256 * 128];            // W_q^T [in][h]
__device__ float g_wkt[256 * 128];            // W_k^T [in][h]
__device__ float g_qp[4 * 256 * 128];         // projected queries
__device__ float g_kp[4 * 1024 * 128];        // projected keys
__device__ float g_pacc[32 * 256 * 256];      // partial acc [b*8+kq][q][v]
__device__ float g_psum[32 * 256];            // partial exp-sums [b*8+kq][q]
__device__ unsigned int g_flag_t;             // transpose-done counter (self-reset)
__device__ unsigned int g_done_p;             // prep completion counter (self-reset)
__device__ unsigned int g_item;               // work-steal counter (self-reset)
__device__ unsigned int g_done_a;             // attn completion counter (self-reset)
__device__ unsigned int g_cnt[256];           // per-(b,qt) partial counters (self-reset)

__device__ __forceinline__ float tanh_apx(float x) {
    float y;
    asm("tanh.approx.f32 %0, %1;" : "=f"(y) : "f"(x));
    return y;
}

__device__ __forceinline__ void fma2(ull& d, ull a, ull b) {
    asm("fma.rn.f32x2 %0, %1, %2, %0;" : "+l"(d) : "l"(a), "l"(b));
}

__device__ __forceinline__ ull pack2(float x) {
    ull r;
    asm("mov.b64 %0, {%1, %1};" : "=l"(r) : "f"(x));
    return r;
}

__device__ __forceinline__ void ldgsts16(uint32_t saddr, const void* g) {
    asm volatile("cp.async.cg.shared.global [%0], [%1], 16;"
                 :: "r"(saddr), "l"(g));
}
__device__ __forceinline__ void cp_commit() {
    asm volatile("cp.async.commit_group;" ::: "memory");
}
__device__ __forceinline__ void cp_wait0() {
    asm volatile("cp.async.wait_group 0;" ::: "memory");
}

// ---------------------------------------------------------------------------
// K_prep: fused weight transpose + projections (unchanged from R10).
// ---------------------------------------------------------------------------
#define SMEM_PREP (36864 + 32768)   // xs2 [256][18]f2 + wt [2][32*128]f

__global__ __launch_bounds__(256, 2) void k_prep(
    const float* __restrict__ queries, const float* __restrict__ keys,
    const float* __restrict__ Wq, const float* __restrict__ Wk) {
    extern __shared__ float psm[];
    float2* xs2 = (float2*)psm;          // [256][18] float2
    float*  wt  = psm + 9216;            // [2][4096] floats
    __shared__ float ttile[32][33];

    int bid = blockIdx.x;
    int t = threadIdx.x;

    if (bid < 64) {
        int m = bid >> 5;
        int tb = bid & 31;
        int hb = tb >> 3, ib = tb & 7;
        const float* W = m ? Wk : Wq;
        float* Wt = m ? g_wkt : g_wqt;
        int c = t & 31, r0 = t >> 5;
        #pragma unroll
        for (int rr = 0; rr < 4; ++rr) {
            int r = r0 * 4 + rr;
            ttile[r][c] = W[(hb * 32 + r) * 256 + ib * 32 + c];
        }
        __syncthreads();
        #pragma unroll
        for (int rr = 0; rr < 4; ++rr) {
            int r = r0 * 4 + rr;
            Wt[(ib * 32 + r) * 128 + hb * 32 + c] = ttile[c][r];
        }
        __threadfence();
        __syncthreads();
        if (t == 0) atomicAdd(&g_flag_t, 1u);
    }

    if (t == 0) {
        while (atomicAdd(&g_flag_t, 0u) < 64u) {}
        __threadfence();
    }
    __syncthreads();

    const float* src;
    const float* Wt;
    float* dst;
    int r0g;
    if (bid < 128) { src = keys;    Wt = g_wkt; dst = g_kp; r0g = bid * 32; }
    else           { src = queries; Wt = g_wqt; dst = g_qp; r0g = (bid - 128) * 32; }

    uint32_t wtaddr = (uint32_t)__cvta_generic_to_shared(wt);
    const float4* Wt4 = (const float4*)Wt;

    #pragma unroll
    for (int n = 0; n < 4; ++n) {
        int idx = t + n * 256;
        ldgsts16(wtaddr + (uint32_t)(idx * 16), Wt4 + idx);
    }
    cp_commit();

    const float4* s4 = (const float4*)(src + r0g * 256);
    float* xsf = (float*)xs2;
    #pragma unroll 4
    for (int n = 0; n < 8; ++n) {
        int idx4 = t + n * 256;
        int r = idx4 >> 6, i4 = idx4 & 63;
        float4 v = s4[idx4];
        xsf[(i4 * 4 + 0) * 36 + r] = v.x;
        xsf[(i4 * 4 + 1) * 36 + r] = v.y;
        xsf[(i4 * 4 + 2) * 36 + r] = v.z;
        xsf[(i4 * 4 + 3) * 36 + r] = v.w;
    }
    cp_wait0();

    int h2 = (t & 63) * 2;
    int rh = t >> 6;
    const float2* xp = xs2 + rh * 4;
    ull acc[4][2] = {{0ull,0ull},{0ull,0ull},{0ull,0ull},{0ull,0ull}};

    for (int tau = 0; tau < 8; ++tau) {
        __syncthreads();
        if (tau + 1 < 8) {
            int buf = (tau + 1) & 1;
            const float4* srcw = Wt4 + (tau + 1) * 1024;
            #pragma unroll
            for (int n = 0; n < 4; ++n) {
                int idx = t + n * 256;
                ldgsts16(wtaddr + (uint32_t)(buf * 16384 + idx * 16), srcw + idx);
            }
            cp_commit();
        }
        const float* wb = wt + (tau & 1) * 4096;
        #pragma unroll 8
        for (int ii = 0; ii < 32; ++ii) {
            float2 w2 = *(const float2*)&wb[ii * 128 + h2];
            ull wa = pack2(w2.x);
            ull wbp = pack2(w2.y);
            const float2* xi = xp + (tau * 32 + ii) * 18;
            ull x0 = *(const ull*)&xi[0];
            ull x1 = *(const ull*)&xi[1];
            ull x2 = *(const ull*)&xi[2];
            ull x3 = *(const ull*)&xi[3];
            fma2(acc[0][0], x0, wa); fma2(acc[0][1], x0, wbp);
            fma2(acc[1][0], x1, wa); fma2(acc[1][1], x1, wbp);
            fma2(acc[2][0], x2, wa); fma2(acc[2][1], x2, wbp);
            fma2(acc[3][0], x3, wa); fma2(acc[3][1], x3, wbp);
        }
        cp_wait0();
    }

    #pragma unroll
    for (int p = 0; p < 4; ++p) {
        float2 A = *(float2*)&acc[p][0];
        float2 Bv = *(float2*)&acc[p][1];
        int r = r0g + rh * 8 + p * 2;
        float2 o0 = make_float2(A.x, Bv.x);
        float2 o1 = make_float2(A.y, Bv.y);
        *(float2*)&dst[r * 128 + h2] = o0;
        *(float2*)&dst[(r + 1) * 128 + h2] = o1;
    }

    __syncthreads();
    if (t == 0) {
        if (atomicAdd(&g_done_p, 1u) == 159u) {
            atomicExch(&g_flag_t, 0u);
            atomicExch(&g_done_p, 0u);
        }
    }
}

// ---------------------------------------------------------------------------
// K_attn7: PERSISTENT split-K attn with work stealing.
// Grid = 444 (3 blocks/SM). 2048 items: item -> b = i&3, kq = (i>>2)&7
// (128-k slice), qt = i>>5 (4-q tile). Items with k0 >= vlen skipped cheaply.
// Per item (R9 geometry): <=2 chunks of 64 k; ks double-buffered cp.async
// (rotation swizzle); Phase A(c) fused with Phase C(c-1); 4 independent score
// chains; e = expf(score), bounded, no max pass; next item claimed during the
// last chunk so the atomic hides under compute. Partials -> g_pacc/g_psum;
// combine-on-last-arrival per (b,qt) over np = ceil(vlen/128) <= 8 partials.
// All counters self-reset (graph replay safe); output order-deterministic.
// ---------------------------------------------------------------------------
#define SMEM_ATTN (65536 + 2048 + 512 + 4096 + 32)
#define N_ITEMS 2048u
#define N_PERSIST 444

__global__ __launch_bounds__(256, 3) void k_attn7(
    const float* __restrict__ values, const int* __restrict__ valid_lens,
    const float* __restrict__ w_v, float* __restrict__ out) {
    extern __shared__ float sm[];
    float4* ks4  = (float4*)sm;                      // [2][2048] float4
    float*  qs   = sm + 16384;                       // [4][128]
    float*  wvs  = qs + 512;                         // [128]
    float2* eb2  = (float2*)(wvs + 128);             // [2][256] = {e,e}
    float*  wsum = (float*)(eb2 + 512);              // [8]
    __shared__ unsigned int s_next, s_old;
    __shared__ int s_vl[4];

    int t = threadIdx.x;
    if (t == 0) s_next = atomicAdd(&g_item, 1u);
    if (t < 4) s_vl[t] = valid_lens[t];
    if (t < 128) wvs[t] = w_v[t];
    __syncthreads();

    int qa = t >> 6;                 // warp-uniform q (0..3)
    int ka = t & 63;                 // A: key index within chunk
    int vp = (t & 63) * 4;           // C: 4 v-cols (perfectly coalesced)
    uint32_t ksaddr = (uint32_t)__cvta_generic_to_shared(ks4);

    for (;;) {
        unsigned int item = s_next;
        if (item >= N_ITEMS) break;
        int b = item & 3;
        int kq = (int)((item >> 2) & 7);
        int qt = (int)(item >> 5);
        int vlen = s_vl[b];
        int k0 = kq * 128;
        if (k0 >= vlen) {            // cheap skip
            __syncthreads();
            if (t == 0) s_next = atomicAdd(&g_item, 1u);
            __syncthreads();
            continue;
        }
        int nch = min(2, (vlen - k0 + 63) >> 6);
        int q0 = qt * 4;
        const float4* kp4 = (const float4*)(g_kp + (b * 1024 + k0) * 128);
        const float* Vb = values + (b * 1024 + k0) * 256;

        // ---- issue chunk 0 into buf0 (prev readers are past a barrier) ----
        #pragma unroll
        for (int n = 0; n < 8; ++n) {
            int idx = t + n * 256;
            int kk = idx >> 5, h4 = idx & 31;
            uint32_t d = ksaddr + (uint32_t)((kk * 32 + ((h4 + kk) & 31)) * 16);
            ldgsts16(d, kp4 + kk * 32 + h4);
        }
        cp_commit();

        // qs for this item (hidden under the copy)
        for (int i = t; i < 512; i += 256)
            qs[i] = g_qp[(b * 256 + q0) * 128 + i];
        cp_wait0();

        ull acc0 = 0ull, acc1 = 0ull;
        float lsum = 0.f;
        const float* qrow = qs + qa * 128;

        for (int c = 0; c < nch; ++c) {
            __syncthreads();   // chunk c + qs visible; ebuf(c-1) visible

            if (c + 1 < nch) {
                const float4* srcc = kp4 + 2048;
                #pragma unroll
                for (int n = 0; n < 8; ++n) {
                    int idx = t + n * 256;
                    int kk = idx >> 5, h4 = idx & 31;
                    uint32_t d = ksaddr +
                        (uint32_t)((2048 + kk * 32 + ((h4 + kk) & 31)) * 16);
                    ldgsts16(d, srcc + kk * 32 + h4);
                }
                cp_commit();
            } else if (t == 0) {
                s_next = atomicAdd(&g_item, 1u);   // claim next under compute
            }

            const float4* ksb = ks4 + (c & 1) * 2048 + ka * 32;
            float s0 = 0.f, s1 = 0.f, s2 = 0.f, s3 = 0.f;

            if (c == 0) {
                #pragma unroll 8
                for (int j = 0; j < 32; ++j) {
                    float4 kv = ksb[(j + ka) & 31];
                    float4 q4 = *(const float4*)&qrow[j * 4];
                    float4 w4 = *(const float4*)&wvs[j * 4];
                    s0 = fmaf(w4.x, tanh_apx(q4.x + kv.x), s0);
                    s1 = fmaf(w4.y, tanh_apx(q4.y + kv.y), s1);
                    s2 = fmaf(w4.z, tanh_apx(q4.z + kv.z), s2);
                    s3 = fmaf(w4.w, tanh_apx(q4.w + kv.w), s3);
                }
            } else {
                const float2* eb = eb2 + ((c & 1) ^ 1) * 256 + qa * 64;
                const float* Vp = Vb + (c - 1) * 64 * 256 + vp;
                #pragma unroll 4
                for (int j = 0; j < 32; ++j) {
                    float4 kv = ksb[(j + ka) & 31];
                    float4 q4 = *(const float4*)&qrow[j * 4];
                    float4 w4 = *(const float4*)&wvs[j * 4];
                    s0 = fmaf(w4.x, tanh_apx(q4.x + kv.x), s0);
                    s1 = fmaf(w4.y, tanh_apx(q4.y + kv.y), s1);
                    s2 = fmaf(w4.z, tanh_apx(q4.z + kv.z), s2);
                    s3 = fmaf(w4.w, tanh_apx(q4.w + kv.w), s3);
                    float2 e0 = eb[2 * j];
                    float2 e1 = eb[2 * j + 1];
                    float4 v0 = *(const float4*)&Vp[(2 * j) * 256];
                    float4 v1 = *(const float4*)&Vp[(2 * j + 1) * 256];
                    fma2(acc0, *(ull*)&e0, *(ull*)&v0.x);
                    fma2(acc1, *(ull*)&e0, *(ull*)&v0.z);
                    fma2(acc0, *(ull*)&e1, *(ull*)&v1.x);
                    fma2(acc1, *(ull*)&e1, *(ull*)&v1.z);
                }
            }

            int kg = k0 + c * 64 + ka;
            float s = (s0 + s1) + (s2 + s3);
            float e = (kg < vlen) ? __expf(s) : 0.f;
            eb2[(c & 1) * 256 + qa * 64 + ka] = make_float2(e, e);
            lsum += e;
            if (c + 1 < nch) cp_wait0();
        }

        // ---- epilogue: C(nch-1); also makes s_next + last ebuf visible ----
        __syncthreads();
        {
            const float2* eb = eb2 + ((nch - 1) & 1) * 256 + qa * 64;
            const float* Vp = Vb + (nch - 1) * 64 * 256 + vp;
            #pragma unroll 4
            for (int kk = 0; kk < 64; ++kk) {
                float2 e0 = eb[kk];
                float4 v0 = *(const float4*)&Vp[kk * 256];
                fma2(acc0, *(ull*)&e0, *(ull*)&v0.x);
                fma2(acc1, *(ull*)&e0, *(ull*)&v0.z);
            }
        }

        // per-q exp sums: warps 2q, 2q+1 cover q
        lsum += __shfl_xor_sync(0xffffffffu, lsum, 16);
        lsum += __shfl_xor_sync(0xffffffffu, lsum, 8);
        lsum += __shfl_xor_sync(0xffffffffu, lsum, 4);
        lsum += __shfl_xor_sync(0xffffffffu, lsum, 2);
        lsum += __shfl_xor_sync(0xffffffffu, lsum, 1);
        int lane = t & 31, w = t >> 5;
        if (lane == 0) wsum[w] = lsum;
        __syncthreads();
        if (t < 4)
            g_psum[(b * 8 + kq) * 256 + q0 + t] = wsum[2 * t] + wsum[2 * t + 1];

        // partial acc write (unnormalized)
        {
            float* pa = &g_pacc[(((b * 8 + kq) * 256) + q0 + qa) * 256 + vp];
            float4 o;
            o.x = ((float2*)&acc0)->x; o.y = ((float2*)&acc0)->y;
            o.z = ((float2*)&acc1)->x; o.w = ((float2*)&acc1)->y;
            *(float4*)pa = o;
        }

        // ---- combine-on-last-arrival ----
        __threadfence();
        __syncthreads();
        if (t == 0) s_old = atomicAdd(&g_cnt[b * 64 + qt], 1u);
        __syncthreads();

        int np = (vlen + 127) >> 7;       // participants 1..8
        if (s_old == (unsigned)(np - 1)) {
            __threadfence();              // acquire: peers' partials visible
            #pragma unroll
            for (int qi = 0; qi < 4; ++qi) {
                int qq = q0 + qi;
                float a = 0.f, ssum = 0.f;
                for (int p = 0; p < np; ++p) {
                    a += g_pacc[((b * 8 + p) * 256 + qq) * 256 + t];
                    ssum += g_psum[(b * 8 + p) * 256 + qq];
                }
                out[(b * 256 + qq) * 256 + t] = a / ssum;
            }
            if (t == 0) atomicExch(&g_cnt[b * 64 + qt], 0u);
        }
        // loop continues with s_next (claimed during last chunk)
    }

    // self-reset steal counter once all persistent blocks are done
    if (t == 0) {
        if (atomicAdd(&g_done_a, 1u) == (unsigned)(N_PERSIST - 1)) {
            atomicExch(&g_item, 0u);
            atomicExch(&g_done_a, 0u);
        }
    }
}

// ---------------------------------------------------------------------------
extern "C" void kernel_launch(void* const* d_in, const int* in_sizes, int n_in,
                              void* d_out, int out_size) {
    const float* queries    = (const float*)d_in[0];  // [4,256,256]
    const float* keys       = (const float*)d_in[1];  // [4,1024,256]
    const float* values     = (const float*)d_in[2];  // [4,1024,256]
    const int*   valid_lens = (const int*)d_in[3];    // [4]
    const float* W_q        = (const float*)d_in[4];  // [128,256]
    const float* W_k        = (const float*)d_in[5];  // [128,256]
    const float* w_v        = (const float*)d_in[6];  // [128]
    float* out = (float*)d_out;                       // [4,256,256]

    cudaFuncSetAttribute(k_prep, cudaFuncAttributeMaxDynamicSharedMemorySize,
                         SMEM_PREP);
    cudaFuncSetAttribute(k_attn7, cudaFuncAttributeMaxDynamicSharedMemorySize,
                         SMEM_ATTN);

    k_prep<<<160, 256, SMEM_PREP>>>(queries, keys, W_q, W_k);
    k_attn7<<<N_PERSIST, 256, SMEM_ATTN>>>(values, valid_lens, w_v, out);
}

// round 13
// speedup vs baseline: 1.3358x; 1.0945x over previous
#include <cuda_runtime.h>
#include <cstdint>

// AdditiveAttention: out[b,q,v] = softmax_k( sum_h w_v[h]*tanh(q~[b,q,h]+k~[b,k,h]) ) @ V
// B=4, Q=256, K=1024, IN=256, H=128, V=256.

typedef unsigned long long ull;

// Scratch (__device__ globals — no allocation allowed)
__device__ float g_wqt[256 * 128];            // W_q^T [in][h]
__device__ float g_wkt[256 * 128];            // W_k^T [in][h]
__device__ float g_qp[4 * 256 * 128];         // projected queries
__device__ float g_kp[4 * 1024 * 128];        // projected keys
__device__ float g_pacc[32 * 256 * 256];      // partial acc [b*8+kq][q][v]
__device__ float g_psum[32 * 256];            // partial exp-sums [b*8+kq][q]
__device__ unsigned int g_flag_t;             // transpose-done counter (self-reset)
__device__ unsigned int g_done_p;             // prep completion counter (self-reset)
__device__ unsigned int g_cnt[64];            // per-(b,qt16) counters (self-reset)

__device__ __forceinline__ float tanh_apx(float x) {
    float y;
    asm("tanh.approx.f32 %0, %1;" : "=f"(y) : "f"(x));
    return y;
}

__device__ __forceinline__ void fma2(ull& d, ull a, ull b) {
    asm("fma.rn.f32x2 %0, %1, %2, %0;" : "+l"(d) : "l"(a), "l"(b));
}

__device__ __forceinline__ ull pack2(float x) {
    ull r;
    asm("mov.b64 %0, {%1, %1};" : "=l"(r) : "f"(x));
    return r;
}

__device__ __forceinline__ void ldgsts16(uint32_t saddr, const void* g) {
    asm volatile("cp.async.cg.shared.global [%0], [%1], 16;"
                 :: "r"(saddr), "l"(g));
}
__device__ __forceinline__ void cp_commit() {
    asm volatile("cp.async.commit_group;" ::: "memory");
}
__device__ __forceinline__ void cp_wait0() {
    asm volatile("cp.async.wait_group 0;" ::: "memory");
}

// ---------------------------------------------------------------------------
// K_prep: fused weight transpose + projections (unchanged from R12 — passing).
// ---------------------------------------------------------------------------
#define SMEM_PREP (36864 + 32768)   // xs2 [256][18]f2 + wt [2][32*128]f

__global__ __launch_bounds__(256, 2) void k_prep(
    const float* __restrict__ queries, const float* __restrict__ keys,
    const float* __restrict__ Wq, const float* __restrict__ Wk) {
    extern __shared__ float psm[];
    float2* xs2 = (float2*)psm;          // [256][18] float2
    float*  wt  = psm + 9216;            // [2][4096] floats
    __shared__ float ttile[32][33];

    int bid = blockIdx.x;
    int t = threadIdx.x;

    if (bid < 64) {
        int m = bid >> 5;
        int tb = bid & 31;
        int hb = tb >> 3, ib = tb & 7;
        const float* W = m ? Wk : Wq;
        float* Wt = m ? g_wkt : g_wqt;
        int c = t & 31, r0 = t >> 5;
        #pragma unroll
        for (int rr = 0; rr < 4; ++rr) {
            int r = r0 * 4 + rr;
            ttile[r][c] = W[(hb * 32 + r) * 256 + ib * 32 + c];
        }
        __syncthreads();
        #pragma unroll
        for (int rr = 0; rr < 4; ++rr) {
            int r = r0 * 4 + rr;
            Wt[(ib * 32 + r) * 128 + hb * 32 + c] = ttile[c][r];
        }
        __threadfence();
        __syncthreads();
        if (t == 0) atomicAdd(&g_flag_t, 1u);
    }

    if (t == 0) {
        while (atomicAdd(&g_flag_t, 0u) < 64u) {}
        __threadfence();
    }
    __syncthreads();

    const float* src;
    const float* Wt;
    float* dst;
    int r0g;
    if (bid < 128) { src = keys;    Wt = g_wkt; dst = g_kp; r0g = bid * 32; }
    else           { src = queries; Wt = g_wqt; dst = g_qp; r0g = (bid - 128) * 32; }

    uint32_t wtaddr = (uint32_t)__cvta_generic_to_shared(wt);
    const float4* Wt4 = (const float4*)Wt;

    #pragma unroll
    for (int n = 0; n < 4; ++n) {
        int idx = t + n * 256;
        ldgsts16(wtaddr + (uint32_t)(idx * 16), Wt4 + idx);
    }
    cp_commit();

    const float4* s4 = (const float4*)(src + r0g * 256);
    float* xsf = (float*)xs2;
    #pragma unroll 4
    for (int n = 0; n < 8; ++n) {
        int idx4 = t + n * 256;
        int r = idx4 >> 6, i4 = idx4 & 63;
        float4 v = s4[idx4];
        xsf[(i4 * 4 + 0) * 36 + r] = v.x;
        xsf[(i4 * 4 + 1) * 36 + r] = v.y;
        xsf[(i4 * 4 + 2) * 36 + r] = v.z;
        xsf[(i4 * 4 + 3) * 36 + r] = v.w;
    }
    cp_wait0();

    int h2 = (t & 63) * 2;
    int rh = t >> 6;
    const float2* xp = xs2 + rh * 4;
    ull acc[4][2] = {{0ull,0ull},{0ull,0ull},{0ull,0ull},{0ull,0ull}};

    for (int tau = 0; tau < 8; ++tau) {
        __syncthreads();
        if (tau + 1 < 8) {
            int buf = (tau + 1) & 1;
            const float4* srcw = Wt4 + (tau + 1) * 1024;
            #pragma unroll
            for (int n = 0; n < 4; ++n) {
                int idx = t + n * 256;
                ldgsts16(wtaddr + (uint32_t)(buf * 16384 + idx * 16), srcw + idx);
            }
            cp_commit();
        }
        const float* wb = wt + (tau & 1) * 4096;
        #pragma unroll 8
        for (int ii = 0; ii < 32; ++ii) {
            float2 w2 = *(const float2*)&wb[ii * 128 + h2];
            ull wa = pack2(w2.x);
            ull wbp = pack2(w2.y);
            const float2* xi = xp + (tau * 32 + ii) * 18;
            ull x0 = *(const ull*)&xi[0];
            ull x1 = *(const ull*)&xi[1];
            ull x2 = *(const ull*)&xi[2];
            ull x3 = *(const ull*)&xi[3];
            fma2(acc[0][0], x0, wa); fma2(acc[0][1], x0, wbp);
            fma2(acc[1][0], x1, wa); fma2(acc[1][1], x1, wbp);
            fma2(acc[2][0], x2, wa); fma2(acc[2][1], x2, wbp);
            fma2(acc[3][0], x3, wa); fma2(acc[3][1], x3, wbp);
        }
        cp_wait0();
    }

    #pragma unroll
    for (int p = 0; p < 4; ++p) {
        float2 A = *(float2*)&acc[p][0];
        float2 Bv = *(float2*)&acc[p][1];
        int r = r0g + rh * 8 + p * 2;
        float2 o0 = make_float2(A.x, Bv.x);
        float2 o1 = make_float2(A.y, Bv.y);
        *(float2*)&dst[r * 128 + h2] = o0;
        *(float2*)&dst[(r + 1) * 128 + h2] = o1;
    }

    __syncthreads();
    if (t == 0) {
        if (atomicAdd(&g_done_p, 1u) == 159u) {
            atomicExch(&g_flag_t, 0u);
            atomicExch(&g_done_p, 0u);
        }
    }
}

// ---------------------------------------------------------------------------
// K_attn8: split-K attn, high arithmetic-intensity mapping.
// 512 blocks: b = bid&3, kq = (bid>>2)&7 (128-k slice), qt = bid>>5 (16-q
// tile). Blocks past vlen exit. Per block: <=2 chunks of 64 k, ks double-
// buffered cp.async with rotation swizzle.
// Phase A: thread (ka = t&63, qg = t>>6) computes 4 scores (q = qg*4+qi) for
//   its k: per j (4 h): 1 ks LDS.128 + 4 q bcast + 1 wv bcast -> 16 tanh.
//   4 independent chains/thread; qg warp-uniform. Crossbar 0.018 cyc/thread-h.
// Phase C (fused, 2 k per j): thread (qc = t>>6 -> 4 q rows, vp=(t&63)*4):
//   per k: 1 V LDG.128 + 4 e bcast + 8 fma2 (4q x 4v).
// Partials -> g_pacc/g_psum; combine-on-last-arrival per (b,qt) over
// np = ceil(vlen/128) <= 8. SMEM ~88.7 KB -> 2 blocks/SM.
// ---------------------------------------------------------------------------
#define SMEM_ATTN (65536 + 8192 + 512 + 16384 + 128)

__global__ __launch_bounds__(256, 2) void k_attn8(
    const float* __restrict__ values, const int* __restrict__ valid_lens,
    const float* __restrict__ w_v, float* __restrict__ out) {
    extern __shared__ float sm[];
    float4* ks4  = (float4*)sm;                      // [2][2048] float4 64KB
    float*  qs   = sm + 16384;                       // [16][128]        8KB
    float*  wvs  = qs + 2048;                        // [128]
    float2* eb2  = (float2*)(wvs + 128);             // [2][16*64] {e,e} 16KB
    float*  wsum = (float*)(eb2 + 2048);             // [8][4]
    __shared__ unsigned int s_old;

    int bid = blockIdx.x;
    int b = bid & 3;
    int kq = (bid >> 2) & 7;
    int qt = bid >> 5;                // 0..15
    int vlen = valid_lens[b];
    int k0 = kq * 128;
    if (k0 >= vlen) return;
    int nch = min(2, (vlen - k0 + 63) >> 6);

    int t = threadIdx.x;
    int q0 = qt * 16;
    int ka = t & 63;                  // A: key within chunk
    int qg = t >> 6;                  // warp-uniform q-group (0..3)
    int vp = (t & 63) * 4;            // C: 4 v-cols, coalesced

    const float4* kp4 = (const float4*)(g_kp + (b * 1024 + k0) * 128);
    const float* Vb = values + (b * 1024 + k0) * 256;
    uint32_t ksaddr = (uint32_t)__cvta_generic_to_shared(ks4);

    // ---- issue chunk 0 copy (64 k x 32 float4) ----
    #pragma unroll
    for (int n = 0; n < 8; ++n) {
        int idx = t + n * 256;
        int kk = idx >> 5, h4 = idx & 31;
        uint32_t d = ksaddr + (uint32_t)((kk * 32 + ((h4 + kk) & 31)) * 16);
        ldgsts16(d, kp4 + kk * 32 + h4);
    }
    cp_commit();

    // ---- load qs (16 rows), wvs while copy flies ----
    for (int i = t; i < 2048; i += 256)
        qs[i] = g_qp[(b * 256 + q0) * 128 + i];
    if (t < 128) wvs[t] = w_v[t];
    cp_wait0();

    ull acc[4][2] = {{0ull,0ull},{0ull,0ull},{0ull,0ull},{0ull,0ull}};
    float lsum[4] = {0.f, 0.f, 0.f, 0.f};
    const float* qbase = qs + qg * 4 * 128;

    for (int c = 0; c < nch; ++c) {
        __syncthreads();   // chunk c + qs visible; eb(c-1) visible

        if (c + 1 < nch) {
            const float4* srcc = kp4 + 2048;
            #pragma unroll
            for (int n = 0; n < 8; ++n) {
                int idx = t + n * 256;
                int kk = idx >> 5, h4 = idx & 31;
                uint32_t d = ksaddr +
                    (uint32_t)((2048 + kk * 32 + ((h4 + kk) & 31)) * 16);
                ldgsts16(d, srcc + kk * 32 + h4);
            }
            cp_commit();
        }

        const float4* ksb = ks4 + (c & 1) * 2048 + ka * 32;
        float s0 = 0.f, s1 = 0.f, s2 = 0.f, s3 = 0.f;   // 4 q chains

        if (c == 0) {
            #pragma unroll 4
            for (int j = 0; j < 32; ++j) {
                float4 kv = ksb[(j + ka) & 31];
                float4 w4 = *(const float4*)&wvs[j * 4];
                float4 qa0 = *(const float4*)&qbase[j * 4];
                float4 qa1 = *(const float4*)&qbase[128 + j * 4];
                float4 qa2 = *(const float4*)&qbase[256 + j * 4];
                float4 qa3 = *(const float4*)&qbase[384 + j * 4];
                s0 = fmaf(w4.x, tanh_apx(qa0.x + kv.x), s0);
                s0 = fmaf(w4.y, tanh_apx(qa0.y + kv.y), s0);
                s0 = fmaf(w4.z, tanh_apx(qa0.z + kv.z), s0);
                s0 = fmaf(w4.w, tanh_apx(qa0.w + kv.w), s0);
                s1 = fmaf(w4.x, tanh_apx(qa1.x + kv.x), s1);
                s1 = fmaf(w4.y, tanh_apx(qa1.y + kv.y), s1);
                s1 = fmaf(w4.z, tanh_apx(qa1.z + kv.z), s1);
                s1 = fmaf(w4.w, tanh_apx(qa1.w + kv.w), s1);
                s2 = fmaf(w4.x, tanh_apx(qa2.x + kv.x), s2);
                s2 = fmaf(w4.y, tanh_apx(qa2.y + kv.y), s2);
                s2 = fmaf(w4.z, tanh_apx(qa2.z + kv.z), s2);
                s2 = fmaf(w4.w, tanh_apx(qa2.w + kv.w), s2);
                s3 = fmaf(w4.x, tanh_apx(qa3.x + kv.x), s3);
                s3 = fmaf(w4.y, tanh_apx(qa3.y + kv.y), s3);
                s3 = fmaf(w4.z, tanh_apx(qa3.z + kv.z), s3);
                s3 = fmaf(w4.w, tanh_apx(qa3.w + kv.w), s3);
            }
        } else {
            const float2* eb = eb2 + ((c & 1) ^ 1) * 1024 + qg * 4 * 64;
            const float* Vp = Vb + (c - 1) * 64 * 256 + vp;
            #pragma unroll 2
            for (int j = 0; j < 32; ++j) {
                float4 kv = ksb[(j + ka) & 31];
                float4 w4 = *(const float4*)&wvs[j * 4];
                float4 qa0 = *(const float4*)&qbase[j * 4];
                float4 qa1 = *(const float4*)&qbase[128 + j * 4];
                float4 qa2 = *(const float4*)&qbase[256 + j * 4];
                float4 qa3 = *(const float4*)&qbase[384 + j * 4];
                s0 = fmaf(w4.x, tanh_apx(qa0.x + kv.x), s0);
                s0 = fmaf(w4.y, tanh_apx(qa0.y + kv.y), s0);
                s0 = fmaf(w4.z, tanh_apx(qa0.z + kv.z), s0);
                s0 = fmaf(w4.w, tanh_apx(qa0.w + kv.w), s0);
                s1 = fmaf(w4.x, tanh_apx(qa1.x + kv.x), s1);
                s1 = fmaf(w4.y, tanh_apx(qa1.y + kv.y), s1);
                s1 = fmaf(w4.z, tanh_apx(qa1.z + kv.z), s1);
                s1 = fmaf(w4.w, tanh_apx(qa1.w + kv.w), s1);
                s2 = fmaf(w4.x, tanh_apx(qa2.x + kv.x), s2);
                s2 = fmaf(w4.y, tanh_apx(qa2.y + kv.y), s2);
                s2 = fmaf(w4.z, tanh_apx(qa2.z + kv.z), s2);
                s2 = fmaf(w4.w, tanh_apx(qa2.w + kv.w), s2);
                s3 = fmaf(w4.x, tanh_apx(qa3.x + kv.x), s3);
                s3 = fmaf(w4.y, tanh_apx(qa3.y + kv.y), s3);
                s3 = fmaf(w4.z, tanh_apx(qa3.z + kv.z), s3);
                s3 = fmaf(w4.w, tanh_apx(qa3.w + kv.w), s3);
                // Phase C of previous chunk: k = 2j, 2j+1
                #pragma unroll
                for (int dk = 0; dk < 2; ++dk) {
                    int kk = 2 * j + dk;
                    float4 v0 = *(const float4*)&Vp[kk * 256];
                    ull v01 = *(ull*)&v0.x, v23 = *(ull*)&v0.z;
                    float2 e0 = eb[kk];
                    float2 e1 = eb[64 + kk];
                    float2 e2 = eb[128 + kk];
                    float2 e3 = eb[192 + kk];
                    fma2(acc[0][0], *(ull*)&e0, v01);
                    fma2(acc[0][1], *(ull*)&e0, v23);
                    fma2(acc[1][0], *(ull*)&e1, v01);
                    fma2(acc[1][1], *(ull*)&e1, v23);
                    fma2(acc[2][0], *(ull*)&e2, v01);
                    fma2(acc[2][1], *(ull*)&e2, v23);
                    fma2(acc[3][0], *(ull*)&e3, v01);
                    fma2(acc[3][1], *(ull*)&e3, v23);
                }
            }
        }

        // exp + store e (duplicated) for 4 q, masked
        int kg = k0 + c * 64 + ka;
        bool valid = (kg < vlen);
        float e0 = valid ? __expf(s0) : 0.f;
        float e1 = valid ? __expf(s1) : 0.f;
        float e2 = valid ? __expf(s2) : 0.f;
        float e3 = valid ? __expf(s3) : 0.f;
        float2* ebw = eb2 + (c & 1) * 1024 + qg * 4 * 64 + ka;
        ebw[0]   = make_float2(e0, e0);
        ebw[64]  = make_float2(e1, e1);
        ebw[128] = make_float2(e2, e2);
        ebw[192] = make_float2(e3, e3);
        lsum[0] += e0; lsum[1] += e1; lsum[2] += e2; lsum[3] += e3;
        if (c + 1 < nch) cp_wait0();
    }

    // ---- epilogue: C(nch-1) ----
    __syncthreads();
    {
        const float2* eb = eb2 + ((nch - 1) & 1) * 1024 + qg * 4 * 64;
        const float* Vp = Vb + (nch - 1) * 64 * 256 + vp;
        #pragma unroll 4
        for (int kk = 0; kk < 64; ++kk) {
            float4 v0 = *(const float4*)&Vp[kk * 256];
            ull v01 = *(ull*)&v0.x, v23 = *(ull*)&v0.z;
            float2 e0 = eb[kk];
            float2 e1 = eb[64 + kk];
            float2 e2 = eb[128 + kk];
            float2 e3 = eb[192 + kk];
            fma2(acc[0][0], *(ull*)&e0, v01);
            fma2(acc[0][1], *(ull*)&e0, v23);
            fma2(acc[1][0], *(ull*)&e1, v01);
            fma2(acc[1][1], *(ull*)&e1, v23);
            fma2(acc[2][0], *(ull*)&e2, v01);
            fma2(acc[2][1], *(ull*)&e2, v23);
            fma2(acc[3][0], *(ull*)&e3, v01);
            fma2(acc[3][1], *(ull*)&e3, v23);
        }
    }

    // per-q exp sums: warp w covers (qg = w>>1, k-half = w&1); 4 chains each
    #pragma unroll
    for (int qi = 0; qi < 4; ++qi) {
        float v = lsum[qi];
        v += __shfl_xor_sync(0xffffffffu, v, 16);
        v += __shfl_xor_sync(0xffffffffu, v, 8);
        v += __shfl_xor_sync(0xffffffffu, v, 4);
        v += __shfl_xor_sync(0xffffffffu, v, 2);
        v += __shfl_xor_sync(0xffffffffu, v, 1);
        lsum[qi] = v;
    }
    int lane = t & 31, w = t >> 5;
    if (lane == 0) {
        wsum[w * 4 + 0] = lsum[0];
        wsum[w * 4 + 1] = lsum[1];
        wsum[w * 4 + 2] = lsum[2];
        wsum[w * 4 + 3] = lsum[3];
    }
    __syncthreads();
    if (t < 16) {
        int g = t >> 2, qi = t & 3;
        g_psum[(b * 8 + kq) * 256 + q0 + g * 4 + qi] =
            wsum[(2 * g) * 4 + qi] + wsum[(2 * g + 1) * 4 + qi];
    }

    // partial acc write: 4 q rows x 4 v per thread
    #pragma unroll
    for (int qi = 0; qi < 4; ++qi) {
        float* pa = &g_pacc[(((b * 8 + kq) * 256) + q0 + qg * 4 + qi) * 256 + vp];
        float4 o;
        o.x = ((float2*)&acc[qi][0])->x; o.y = ((float2*)&acc[qi][0])->y;
        o.z = ((float2*)&acc[qi][1])->x; o.w = ((float2*)&acc[qi][1])->y;
        *(float4*)pa = o;
    }

    // ---- combine-on-last-arrival per (b, qt) ----
    __threadfence();
    __syncthreads();
    if (t == 0) s_old = atomicAdd(&g_cnt[b * 16 + qt], 1u);
    __syncthreads();

    int np = (vlen + 127) >> 7;           // participants 1..8
    if (s_old == (unsigned)(np - 1)) {
        __threadfence();                  // acquire: peers' partials visible
        for (int qi = 0; qi < 16; ++qi) {
            int qq = q0 + qi;
            float a = 0.f, ssum = 0.f;
            for (int p = 0; p < np; ++p) {
                a += g_pacc[((b * 8 + p) * 256 + qq) * 256 + t];
                ssum += g_psum[(b * 8 + p) * 256 + qq];
            }
            out[(b * 256 + qq) * 256 + t] = a / ssum;
        }
        if (t == 0) atomicExch(&g_cnt[b * 16 + qt], 0u);
    }
}

// ---------------------------------------------------------------------------
extern "C" void kernel_launch(void* const* d_in, const int* in_sizes, int n_in,
                              void* d_out, int out_size) {
    const float* queries    = (const float*)d_in[0];  // [4,256,256]
    const float* keys       = (const float*)d_in[1];  // [4,1024,256]
    const float* values     = (const float*)d_in[2];  // [4,1024,256]
    const int*   valid_lens = (const int*)d_in[3];    // [4]
    const float* W_q        = (const float*)d_in[4];  // [128,256]
    const float* W_k        = (const float*)d_in[5];  // [128,256]
    const float* w_v        = (const float*)d_in[6];  // [128]
    float* out = (float*)d_out;                       // [4,256,256]

    cudaFuncSetAttribute(k_prep, cudaFuncAttributeMaxDynamicSharedMemorySize,
                         SMEM_PREP);
    cudaFuncSetAttribute(k_attn8, cudaFuncAttributeMaxDynamicSharedMemorySize,
                         SMEM_ATTN);

    k_prep<<<160, 256, SMEM_PREP>>>(queries, keys, W_q, W_k);
    k_attn8<<<512, 256, SMEM_ATTN>>>(values, valid_lens, w_v, out);
}